// round 3
// baseline (speedup 1.0000x reference)
#include <cuda_runtime.h>

#define NN0 100000
#define NN1 25000
#define NN2 6250
#define EE0 600000
#define EE1 150000
#define EE2 37500

// ---------------- scratch (device globals; no allocations allowed) ----------
__device__ float g_dinv0[NN0], g_dinv1[NN1], g_dinv2[NN2];
__device__ float g_w0[EE0], g_w1[EE1], g_w2[EE2];
__device__ float g_T0[(size_t)NN0 * 18];
__device__ float g_h0[(size_t)NN0 * 128];
__device__ float g_p1[(size_t)NN1 * 128];
__device__ float g_T1[(size_t)NN1 * 768];
__device__ float g_h1[(size_t)NN1 * 128];
__device__ float g_p2[(size_t)NN2 * 128];
__device__ float g_T2[(size_t)NN2 * 768];
__device__ float g_h2[(size_t)NN2 * 256];

// ---------------- small kernels ---------------------------------------------
__global__ void zero_k(float* __restrict__ p, int n) {
    int i = blockIdx.x * blockDim.x + threadIdx.x;
    if (i < n) p[i] = 0.f;
}

__global__ void deg_k(const int* __restrict__ ei, int E, float* __restrict__ deg) {
    int e = blockIdx.x * blockDim.x + threadIdx.x;
    if (e < E) atomicAdd(&deg[ei[e]], 1.f);
}

__global__ void dinv_k(float* __restrict__ d, int n) {
    int i = blockIdx.x * blockDim.x + threadIdx.x;
    if (i < n) { float v = d[i]; d[i] = v > 0.f ? rsqrtf(v) : 0.f; }
}

__global__ void ew_k(const int* __restrict__ ei, int E,
                     const float* __restrict__ dinv, float* __restrict__ w) {
    int e = blockIdx.x * blockDim.x + threadIdx.x;
    if (e < E) w[e] = -dinv[ei[e]] * dinv[ei[E + e]];
}

// T[:, 0:F] = src (src is [n,F] contiguous)
__global__ void copy_col_k(float* __restrict__ T, const float* __restrict__ src,
                           int n, int F, int RS) {
    int i = blockIdx.x * blockDim.x + threadIdx.x;
    if (i >= n * F) return;
    int node = i / F, f = i % F;
    T[(size_t)node * RS + f] = src[i];
}

// T[:, out_off:out_off+F] = neg ? -T[:, in_off:...] : 0
__global__ void set_col_k(float* __restrict__ T, int n, int F, int RS,
                          int out_off, int in_off, int neg) {
    int i = blockIdx.x * blockDim.x + threadIdx.x;
    if (i >= n * F) return;
    int node = i / F, f = i % F;
    float v = neg ? -T[(size_t)node * RS + in_off + f] : 0.f;
    T[(size_t)node * RS + out_off + f] = v;
}

// layer0 propagation: F=3, thread per edge
__global__ void scatter3_k(const int* __restrict__ ei, int E,
                           const float* __restrict__ w, float coef,
                           float* __restrict__ T, int in_off, int out_off) {
    int e = blockIdx.x * blockDim.x + threadIdx.x;
    if (e >= E) return;
    int s = ei[e], d = ei[E + e];
    float cw = coef * w[e];
    const float* in = T + (size_t)s * 18 + in_off;
    float* out = T + (size_t)d * 18 + out_off;
    atomicAdd(&out[0], cw * in[0]);
    atomicAdd(&out[1], cw * in[1]);
    atomicAdd(&out[2], cw * in[2]);
}

// F=128 propagation: warp per edge
__global__ void scatter128_k(const int* __restrict__ ei, int E,
                             const float* __restrict__ w, float coef,
                             float* __restrict__ T, int RS, int in_off, int out_off) {
    int gw = (blockIdx.x * blockDim.x + threadIdx.x) >> 5;
    int lane = threadIdx.x & 31;
    if (gw >= E) return;
    int s = ei[gw], d = ei[E + gw];
    float cw = coef * w[gw];
    const float* in = T + (size_t)s * RS + in_off;
    float* out = T + (size_t)d * RS + out_off;
#pragma unroll
    for (int f = lane; f < 128; f += 32) atomicAdd(&out[f], cw * in[f]);
}

// pool: warp per sparse entry, F=128
__global__ void pool128_k(const int* __restrict__ rows, const int* __restrict__ cols,
                          const float* __restrict__ vals, int E,
                          const float* __restrict__ in, float* __restrict__ out) {
    int gw = (blockIdx.x * blockDim.x + threadIdx.x) >> 5;
    int lane = threadIdx.x & 31;
    if (gw >= E) return;
    int r = rows[gw], c = cols[gw];
    float v = vals[gw];
    const float* ip = in + (size_t)c * 128;
    float* op = out + (size_t)r * 128;
#pragma unroll
    for (int f = lane; f < 128; f += 32) atomicAdd(&op[f], v * ip[f]);
}

// ---------------- GEMM: C[M,N] = act(A[M,K] @ B[K,N] + bias) ----------------
template <bool RELU>
__global__ void __launch_bounds__(256) gemm_k(const float* __restrict__ A,
                                              const float* __restrict__ B,
                                              const float* __restrict__ bias,
                                              float* __restrict__ C,
                                              int M, int N, int K) {
    const int BM = 64, BN = 64, BK = 16, TM = 4, TN = 4;
    __shared__ float As[BK][BM + 4];
    __shared__ float Bs[BK][BN + 4];
    int brow = blockIdx.y * BM, bcol = blockIdx.x * BN;
    int tid = threadIdx.x;
    int tcol = (tid % 16) * TN;
    int trow = (tid / 16) * TM;
    float acc[TM][TN] = {};
    for (int kk = 0; kk < K; kk += BK) {
        for (int i = tid; i < BM * BK; i += 256) {
            int r = i / BK, c = i % BK;
            int gr = brow + r, gc = kk + c;
            As[c][r] = (gr < M && gc < K) ? A[(size_t)gr * K + gc] : 0.f;
        }
        for (int i = tid; i < BK * BN; i += 256) {
            int r = i / BN, c = i % BN;
            int gr = kk + r, gc = bcol + c;
            Bs[r][c] = (gr < K && gc < N) ? B[(size_t)gr * N + gc] : 0.f;
        }
        __syncthreads();
#pragma unroll
        for (int k = 0; k < BK; k++) {
            float ra[TM], rb[TN];
#pragma unroll
            for (int i = 0; i < TM; i++) ra[i] = As[k][trow + i];
#pragma unroll
            for (int j = 0; j < TN; j++) rb[j] = Bs[k][tcol + j];
#pragma unroll
            for (int i = 0; i < TM; i++)
#pragma unroll
                for (int j = 0; j < TN; j++) acc[i][j] = fmaf(ra[i], rb[j], acc[i][j]);
        }
        __syncthreads();
    }
#pragma unroll
    for (int i = 0; i < TM; i++) {
        int gr = brow + trow + i;
        if (gr >= M) continue;
#pragma unroll
        for (int j = 0; j < TN; j++) {
            int gc = bcol + tcol + j;
            float v = acc[i][j] + bias[gc];
            if (RELU) v = fmaxf(v, 0.f);
            C[(size_t)gr * N + gc] = v;
        }
    }
}

// ---------------- final linear ----------------------------------------------
__global__ void initout_k(const float* __restrict__ linb, float* __restrict__ out) {
    int i = threadIdx.x;
    if (i < 10) out[i] = linb[i];
}

__global__ void final_k(const float* __restrict__ h, const float* __restrict__ W,
                        float* __restrict__ out) {
    const int NT = NN2 * 256;
    float acc[10];
#pragma unroll
    for (int r = 0; r < 10; r++) acc[r] = 0.f;
    int stride = gridDim.x * blockDim.x;
    for (int idx = blockIdx.x * blockDim.x + threadIdx.x; idx < NT; idx += stride) {
        float hv = h[idx];
#pragma unroll
        for (int r = 0; r < 10; r++) acc[r] = fmaf(W[(size_t)r * NT + idx], hv, acc[r]);
    }
#pragma unroll
    for (int off = 16; off; off >>= 1)
#pragma unroll
        for (int r = 0; r < 10; r++) acc[r] += __shfl_down_sync(0xffffffffu, acc[r], off);
    if ((threadIdx.x & 31) == 0)
        for (int r = 0; r < 10; r++) atomicAdd(&out[r], acc[r]);
}

// ---------------- host orchestration ----------------------------------------
static inline int cdiv(int a, int b) { return (a + b - 1) / b; }

extern "C" void kernel_launch(void* const* d_in, const int* in_sizes, int n_in,
                              void* d_out, int out_size) {
    const float* x    = (const float*)d_in[0];
    const int*   ei0  = (const int*)d_in[1];
    const int*   ei1  = (const int*)d_in[2];
    const int*   ei2  = (const int*)d_in[3];
    const float* W0   = (const float*)d_in[4];
    const float* b0   = (const float*)d_in[5];
    const float* W1   = (const float*)d_in[6];
    const float* b1   = (const float*)d_in[7];
    const float* W2   = (const float*)d_in[8];
    const float* b2   = (const float*)d_in[9];
    const int*   D0r  = (const int*)d_in[10];
    const int*   D0c  = (const int*)d_in[11];
    const float* D0v  = (const float*)d_in[12];
    const int*   D1r  = (const int*)d_in[13];
    const int*   D1c  = (const int*)d_in[14];
    const float* D1v  = (const float*)d_in[15];
    const float* linW = (const float*)d_in[16];
    const float* linb = (const float*)d_in[17];
    float* out = (float*)d_out;

    float *dinv0, *dinv1, *dinv2, *w0, *w1, *w2;
    float *T0, *h0, *p1, *T1, *h1, *p2, *T2, *h2;
    cudaGetSymbolAddress((void**)&dinv0, g_dinv0);
    cudaGetSymbolAddress((void**)&dinv1, g_dinv1);
    cudaGetSymbolAddress((void**)&dinv2, g_dinv2);
    cudaGetSymbolAddress((void**)&w0, g_w0);
    cudaGetSymbolAddress((void**)&w1, g_w1);
    cudaGetSymbolAddress((void**)&w2, g_w2);
    cudaGetSymbolAddress((void**)&T0, g_T0);
    cudaGetSymbolAddress((void**)&h0, g_h0);
    cudaGetSymbolAddress((void**)&p1, g_p1);
    cudaGetSymbolAddress((void**)&T1, g_T1);
    cudaGetSymbolAddress((void**)&h1, g_h1);
    cudaGetSymbolAddress((void**)&p2, g_p2);
    cudaGetSymbolAddress((void**)&T2, g_T2);
    cudaGetSymbolAddress((void**)&h2, g_h2);

    const int TB = 256;

    // ---- normalized edge weights for the 3 graphs ----
    zero_k<<<cdiv(NN0, TB), TB>>>(dinv0, NN0);
    deg_k<<<cdiv(EE0, TB), TB>>>(ei0, EE0, dinv0);
    dinv_k<<<cdiv(NN0, TB), TB>>>(dinv0, NN0);
    ew_k<<<cdiv(EE0, TB), TB>>>(ei0, EE0, dinv0, w0);

    zero_k<<<cdiv(NN1, TB), TB>>>(dinv1, NN1);
    deg_k<<<cdiv(EE1, TB), TB>>>(ei1, EE1, dinv1);
    dinv_k<<<cdiv(NN1, TB), TB>>>(dinv1, NN1);
    ew_k<<<cdiv(EE1, TB), TB>>>(ei1, EE1, dinv1, w1);

    zero_k<<<cdiv(NN2, TB), TB>>>(dinv2, NN2);
    deg_k<<<cdiv(EE2, TB), TB>>>(ei2, EE2, dinv2);
    dinv_k<<<cdiv(NN2, TB), TB>>>(dinv2, NN2);
    ew_k<<<cdiv(EE2, TB), TB>>>(ei2, EE2, dinv2, w2);

    // ---- layer 0: N0 nodes, F=3, RS=18 ----
    {
        int nF = NN0 * 3;
        copy_col_k<<<cdiv(nF, TB), TB>>>(T0, x, NN0, 3, 18);
        set_col_k<<<cdiv(nF, TB), TB>>>(T0, NN0, 3, 18, 3, 0, 0);
        scatter3_k<<<cdiv(EE0, TB), TB>>>(ei0, EE0, w0, 1.f, T0, 0, 3);
        for (int k = 2; k < 6; k++) {
            set_col_k<<<cdiv(nF, TB), TB>>>(T0, NN0, 3, 18, 3 * k, 3 * (k - 2), 1);
            scatter3_k<<<cdiv(EE0, TB), TB>>>(ei0, EE0, w0, 2.f, T0, 3 * (k - 1), 3 * k);
        }
        dim3 grid(cdiv(128, 64), cdiv(NN0, 64));
        gemm_k<true><<<grid, 256>>>(T0, W0, b0, h0, NN0, 128, 18);
    }

    // ---- pool 0: [N0,128] -> [N1,128] ----
    zero_k<<<cdiv(NN1 * 128, TB), TB>>>(p1, NN1 * 128);
    pool128_k<<<cdiv(100000 * 32, TB), TB>>>(D0r, D0c, D0v, 100000, h0, p1);

    // ---- layer 1: N1 nodes, F=128, RS=768 ----
    {
        int nF = NN1 * 128;
        copy_col_k<<<cdiv(nF, TB), TB>>>(T1, p1, NN1, 128, 768);
        set_col_k<<<cdiv(nF, TB), TB>>>(T1, NN1, 128, 768, 128, 0, 0);
        scatter128_k<<<cdiv(EE1 * 32, TB), TB>>>(ei1, EE1, w1, 1.f, T1, 768, 0, 128);
        for (int k = 2; k < 6; k++) {
            set_col_k<<<cdiv(nF, TB), TB>>>(T1, NN1, 128, 768, 128 * k, 128 * (k - 2), 1);
            scatter128_k<<<cdiv(EE1 * 32, TB), TB>>>(ei1, EE1, w1, 2.f, T1, 768,
                                                     128 * (k - 1), 128 * k);
        }
        dim3 grid(cdiv(128, 64), cdiv(NN1, 64));
        gemm_k<true><<<grid, 256>>>(T1, W1, b1, h1, NN1, 128, 768);
    }

    // ---- pool 1: [N1,128] -> [N2,128] ----
    zero_k<<<cdiv(NN2 * 128, TB), TB>>>(p2, NN2 * 128);
    pool128_k<<<cdiv(25000 * 32, TB), TB>>>(D1r, D1c, D1v, 25000, h1, p2);

    // ---- layer 2: N2 nodes, F=128, RS=768, out=256, no relu ----
    {
        int nF = NN2 * 128;
        copy_col_k<<<cdiv(nF, TB), TB>>>(T2, p2, NN2, 128, 768);
        set_col_k<<<cdiv(nF, TB), TB>>>(T2, NN2, 128, 768, 128, 0, 0);
        scatter128_k<<<cdiv(EE2 * 32, TB), TB>>>(ei2, EE2, w2, 1.f, T2, 768, 0, 128);
        for (int k = 2; k < 6; k++) {
            set_col_k<<<cdiv(nF, TB), TB>>>(T2, NN2, 128, 768, 128 * k, 128 * (k - 2), 1);
            scatter128_k<<<cdiv(EE2 * 32, TB), TB>>>(ei2, EE2, w2, 2.f, T2, 768,
                                                     128 * (k - 1), 128 * k);
        }
        dim3 grid(cdiv(256, 64), cdiv(NN2, 64));
        gemm_k<false><<<grid, 256>>>(T2, W2, b2, h2, NN2, 256, 768);
    }

    // ---- final linear: Z = linW @ h2.flatten + linb ----
    initout_k<<<1, 32>>>(linb, out);
    final_k<<<1184, 256>>>(h2, linW, out);
}

// round 4
// speedup vs baseline: 2.3024x; 2.3024x over previous
#include <cuda_runtime.h>

#define NN0 100000
#define NN1 25000
#define NN2 6250
#define EE0 600000
#define EE1 150000
#define EE2 37500

// ---------------- scratch (device globals; no allocations allowed) ----------
__device__ float g_dinv0[NN0], g_dinv1[NN1], g_dinv2[NN2];
__device__ float g_w0[EE0], g_w1[EE1], g_w2[EE2];
__device__ float g_T0[(size_t)NN0 * 18];
__device__ float g_h0[(size_t)NN0 * 128];
__device__ float g_T1[(size_t)NN1 * 768];
__device__ float g_h1[(size_t)NN1 * 128];
__device__ float g_T2[(size_t)NN2 * 768];
__device__ float g_h2[(size_t)NN2 * 256];

static inline int cdiv(int a, int b) { return (a + b - 1) / b; }

// ---------------- helpers ----------------------------------------------------
__device__ __forceinline__ float tf32r(float x) {
    unsigned u;
    asm("cvt.rna.tf32.f32 %0, %1;" : "=r"(u) : "f"(x));
    return __uint_as_float(u);
}

__device__ __forceinline__ void red4(float* p, float a, float b, float c, float d) {
    asm volatile("red.global.add.v4.f32 [%0], {%1,%2,%3,%4};"
                 :: "l"(p), "f"(a), "f"(b), "f"(c), "f"(d) : "memory");
}

__device__ __forceinline__ void mma_tf32(float& c0, float& c1, float& c2, float& c3,
                                         unsigned a0, unsigned a1, unsigned a2, unsigned a3,
                                         unsigned b0, unsigned b1) {
    asm volatile(
        "mma.sync.aligned.m16n8k8.row.col.f32.tf32.tf32.f32 "
        "{%0,%1,%2,%3},{%4,%5,%6,%7},{%8,%9},{%0,%1,%2,%3};"
        : "+f"(c0), "+f"(c1), "+f"(c2), "+f"(c3)
        : "r"(a0), "r"(a1), "r"(a2), "r"(a3), "r"(b0), "r"(b1));
}

// ---------------- fused preprocessing (all 3 graphs) -------------------------
__global__ void zero_all_k(float* d0, float* d1, float* d2) {
    int i = blockIdx.x * blockDim.x + threadIdx.x;
    if (i < NN0) d0[i] = 0.f;
    int j = i - NN0;
    if (j >= 0 && j < NN1) d1[j] = 0.f;
    int k = j - NN1;
    if (k >= 0 && k < NN2) d2[k] = 0.f;
}

__global__ void deg_all_k(const int* e0, const int* e1, const int* e2,
                          float* d0, float* d1, float* d2) {
    int i = blockIdx.x * blockDim.x + threadIdx.x;
    if (i < EE0) { atomicAdd(&d0[e0[i]], 1.f); return; }
    i -= EE0;
    if (i < EE1) { atomicAdd(&d1[e1[i]], 1.f); return; }
    i -= EE1;
    if (i < EE2) atomicAdd(&d2[e2[i]], 1.f);
}

__global__ void dinv_all_k(float* d0, float* d1, float* d2) {
    int i = blockIdx.x * blockDim.x + threadIdx.x;
    if (i < NN0) { float v = d0[i]; d0[i] = v > 0.f ? rsqrtf(v) : 0.f; }
    int j = i - NN0;
    if (j >= 0 && j < NN1) { float v = d1[j]; d1[j] = v > 0.f ? rsqrtf(v) : 0.f; }
    int k = j - NN1;
    if (k >= 0 && k < NN2) { float v = d2[k]; d2[k] = v > 0.f ? rsqrtf(v) : 0.f; }
}

__global__ void ew_all_k(const int* e0, const int* e1, const int* e2,
                         const float* d0, const float* d1, const float* d2,
                         float* w0, float* w1, float* w2) {
    int i = blockIdx.x * blockDim.x + threadIdx.x;
    if (i < EE0) { w0[i] = -d0[e0[i]] * d0[e0[EE0 + i]]; return; }
    i -= EE0;
    if (i < EE1) { w1[i] = -d1[e1[i]] * d1[e1[EE1 + i]]; return; }
    i -= EE1;
    if (i < EE2) w2[i] = -d2[e2[i]] * d2[e2[EE2 + i]];
}

// ---------------- layer-0 (F=3) ----------------------------------------------
// T0[:,0:3] = x, T0[:,3:6] = 0
__global__ void initT0_k(float* __restrict__ T, const float* __restrict__ x) {
    int i = blockIdx.x * blockDim.x + threadIdx.x;
    if (i >= NN0 * 6) return;
    int node = i / 6, f = i % 6;
    T[node * 18 + f] = f < 3 ? x[node * 3 + f] : 0.f;
}

// scatter (col out_off += coef*w*col in_off) fused with set(col set_dst = -col set_src)
__global__ void fused3_k(const int* __restrict__ ei, int E,
                         const float* __restrict__ w, float coef,
                         float* __restrict__ T, int in_off, int out_off,
                         int set_dst, int set_src, int setBlocks) {
    if ((int)blockIdx.x < setBlocks) {
        int i = blockIdx.x * blockDim.x + threadIdx.x;
        if (i < NN0 * 3) {
            int node = i / 3, f = i % 3;
            T[node * 18 + set_dst + f] = -T[node * 18 + set_src + f];
        }
        return;
    }
    int e = (blockIdx.x - setBlocks) * blockDim.x + threadIdx.x;
    if (e >= E) return;
    int s = ei[e], d = ei[E + e];
    float cw = coef * w[e];
    const float* in = T + s * 18 + in_off;
    float* out = T + d * 18 + out_off;
    atomicAdd(&out[0], cw * in[0]);
    atomicAdd(&out[1], cw * in[1]);
    atomicAdd(&out[2], cw * in[2]);
}

// h0 = relu(T0[N0,18] @ W[18,128] + b), W in smem, warp per node, float4 out
__global__ void __launch_bounds__(256) gemm0_k(const float* __restrict__ T,
                                               const float* __restrict__ W,
                                               const float* __restrict__ bias,
                                               float* __restrict__ out) {
    __shared__ float Ws[18 * 128];
    __shared__ float Bsm[128];
    int tid = threadIdx.x;
    for (int i = tid; i < 18 * 128; i += 256) Ws[i] = W[i];
    if (tid < 128) Bsm[tid] = bias[tid];
    __syncthreads();
    int node = blockIdx.x * 8 + (tid >> 5);
    if (node >= NN0) return;
    int c0 = (tid & 31) * 4;
    const float* tr = T + node * 18;
    float a0 = Bsm[c0], a1 = Bsm[c0 + 1], a2 = Bsm[c0 + 2], a3 = Bsm[c0 + 3];
#pragma unroll
    for (int k = 0; k < 18; k++) {
        float t = tr[k];
        const float4 w4 = *(const float4*)(Ws + k * 128 + c0);
        a0 = fmaf(t, w4.x, a0); a1 = fmaf(t, w4.y, a1);
        a2 = fmaf(t, w4.z, a2); a3 = fmaf(t, w4.w, a3);
    }
    float4 r = make_float4(fmaxf(a0, 0.f), fmaxf(a1, 0.f), fmaxf(a2, 0.f), fmaxf(a3, 0.f));
    *(float4*)(out + (size_t)node * 128 + c0) = r;
}

// ---------------- F=128 layers ------------------------------------------------
// zero cols 0 and 1 (256 floats) of T, stride 768
__global__ void zero2_k(float* __restrict__ T, int n) {
    int i = blockIdx.x * blockDim.x + threadIdx.x;
    if (i >= n * 64) return;
    int node = i >> 6, q = i & 63;
    *(float4*)(T + (size_t)node * 768 + q * 4) = make_float4(0.f, 0.f, 0.f, 0.f);
}

// pool directly into T col 0 (stride 768); warp per entry, float4 + red.v4
__global__ void pool_k(const int* __restrict__ rows, const int* __restrict__ cols,
                       const float* __restrict__ vals, int E,
                       const float* __restrict__ in, float* __restrict__ T) {
    int gw = (blockIdx.x * blockDim.x + threadIdx.x) >> 5;
    int lane = threadIdx.x & 31;
    if (gw >= E) return;
    int r = rows[gw], c = cols[gw];
    float v = vals[gw];
    float4 x = *(const float4*)(in + (size_t)c * 128 + lane * 4);
    red4(T + (size_t)r * 768 + lane * 4, v * x.x, v * x.y, v * x.z, v * x.w);
}

// fused scatter(col out_off += coef*w*col in_off) + set(col set_dst)
// set_src >= 0: init -T[set_src]; set handled by first setBlocks blocks
__global__ void fused128_k(const int* __restrict__ ei, int E,
                           const float* __restrict__ w, float coef,
                           float* __restrict__ T, int in_off, int out_off,
                           int set_dst, int set_src, int n, int setBlocks) {
    if ((int)blockIdx.x < setBlocks) {
        int i = blockIdx.x * blockDim.x + threadIdx.x;
        if (i < n * 32) {
            int node = i >> 5, q = i & 31;
            float4 s = *(const float4*)(T + (size_t)node * 768 + set_src + q * 4);
            *(float4*)(T + (size_t)node * 768 + set_dst + q * 4) =
                make_float4(-s.x, -s.y, -s.z, -s.w);
        }
        return;
    }
    int gw = ((blockIdx.x - setBlocks) * blockDim.x + threadIdx.x) >> 5;
    int lane = threadIdx.x & 31;
    if (gw >= E) return;
    int s = ei[gw], d = ei[E + gw];
    float cw = coef * w[gw];
    float4 x = *(const float4*)(T + (size_t)s * 768 + in_off + lane * 4);
    red4(T + (size_t)d * 768 + out_off + lane * 4, cw * x.x, cw * x.y, cw * x.z, cw * x.w);
}

// ---------------- tf32 tensor-core GEMM --------------------------------------
// C[M,N] = act(A[M,K] @ B[K,N] + bias); BM=64 BN=128 BK=16; 256 thr, 8 warps
// warp tile 32x32 (2x4 warp grid); m16n8k8 tf32 mma
template <bool RELU>
__global__ void __launch_bounds__(256) gemm_tf32_k(const float* __restrict__ A,
                                                   const float* __restrict__ B,
                                                   const float* __restrict__ bias,
                                                   float* __restrict__ C,
                                                   int M, int N, int K) {
    __shared__ float As[2][16][68];
    __shared__ float Bs[2][16][132];
    const int tid = threadIdx.x;
    const int warp = tid >> 5, lane = tid & 31;
    const int g = lane >> 2, tg = lane & 3;
    const int m0 = (warp >> 2) * 32, n0 = (warp & 3) * 32;
    const int brow = blockIdx.y * 64, bcol = blockIdx.x * 128;

    const int am = tid >> 2, akq = (tid & 3) << 2;      // A: row am, k quad akq
    const int bk = tid >> 5, bn4 = (tid & 31) << 2;     // B: rows bk, bk+8, col bn4

    float acc[2][4][4];
#pragma unroll
    for (int i = 0; i < 2; i++)
#pragma unroll
        for (int j = 0; j < 4; j++)
#pragma unroll
            for (int q = 0; q < 4; q++) acc[i][j][q] = 0.f;

    const int KT = K / 16;
    float4 pa, pb0, pb1;

    // prologue: load stage 0
    {
        int gr = brow + am;
        pa = (gr < M) ? *(const float4*)(A + (size_t)gr * K + akq)
                      : make_float4(0.f, 0.f, 0.f, 0.f);
        pb0 = *(const float4*)(B + (size_t)bk * N + bcol + bn4);
        pb1 = *(const float4*)(B + (size_t)(bk + 8) * N + bcol + bn4);
        As[0][akq + 0][am] = tf32r(pa.x); As[0][akq + 1][am] = tf32r(pa.y);
        As[0][akq + 2][am] = tf32r(pa.z); As[0][akq + 3][am] = tf32r(pa.w);
        *(float4*)&Bs[0][bk][bn4] =
            make_float4(tf32r(pb0.x), tf32r(pb0.y), tf32r(pb0.z), tf32r(pb0.w));
        *(float4*)&Bs[0][bk + 8][bn4] =
            make_float4(tf32r(pb1.x), tf32r(pb1.y), tf32r(pb1.z), tf32r(pb1.w));
    }
    __syncthreads();

    for (int t = 0; t < KT; t++) {
        const int st = t & 1;
        if (t + 1 < KT) {
            int kk = (t + 1) * 16;
            int gr = brow + am;
            pa = (gr < M) ? *(const float4*)(A + (size_t)gr * K + kk + akq)
                          : make_float4(0.f, 0.f, 0.f, 0.f);
            pb0 = *(const float4*)(B + (size_t)(kk + bk) * N + bcol + bn4);
            pb1 = *(const float4*)(B + (size_t)(kk + bk + 8) * N + bcol + bn4);
        }
#pragma unroll
        for (int ks = 0; ks < 16; ks += 8) {
            unsigned af[2][4], bf[4][2];
#pragma unroll
            for (int mt = 0; mt < 2; mt++) {
                int mr = m0 + mt * 16 + g;
                af[mt][0] = __float_as_uint(As[st][ks + tg][mr]);
                af[mt][1] = __float_as_uint(As[st][ks + tg][mr + 8]);
                af[mt][2] = __float_as_uint(As[st][ks + tg + 4][mr]);
                af[mt][3] = __float_as_uint(As[st][ks + tg + 4][mr + 8]);
            }
#pragma unroll
            for (int nt = 0; nt < 4; nt++) {
                int nc = n0 + nt * 8 + g;
                bf[nt][0] = __float_as_uint(Bs[st][ks + tg][nc]);
                bf[nt][1] = __float_as_uint(Bs[st][ks + tg + 4][nc]);
            }
#pragma unroll
            for (int mt = 0; mt < 2; mt++)
#pragma unroll
                for (int nt = 0; nt < 4; nt++)
                    mma_tf32(acc[mt][nt][0], acc[mt][nt][1], acc[mt][nt][2], acc[mt][nt][3],
                             af[mt][0], af[mt][1], af[mt][2], af[mt][3],
                             bf[nt][0], bf[nt][1]);
        }
        __syncthreads();
        if (t + 1 < KT) {
            const int ns = (t + 1) & 1;
            As[ns][akq + 0][am] = tf32r(pa.x); As[ns][akq + 1][am] = tf32r(pa.y);
            As[ns][akq + 2][am] = tf32r(pa.z); As[ns][akq + 3][am] = tf32r(pa.w);
            *(float4*)&Bs[ns][bk][bn4] =
                make_float4(tf32r(pb0.x), tf32r(pb0.y), tf32r(pb0.z), tf32r(pb0.w));
            *(float4*)&Bs[ns][bk + 8][bn4] =
                make_float4(tf32r(pb1.x), tf32r(pb1.y), tf32r(pb1.z), tf32r(pb1.w));
            __syncthreads();
        }
    }

    // epilogue
#pragma unroll
    for (int mt = 0; mt < 2; mt++) {
        int r0 = brow + m0 + mt * 16 + g;
        int r1 = r0 + 8;
#pragma unroll
        for (int nt = 0; nt < 4; nt++) {
            int cb = bcol + n0 + nt * 8 + 2 * tg;
            float bx = bias[cb], by = bias[cb + 1];
            float v0 = acc[mt][nt][0] + bx, v1 = acc[mt][nt][1] + by;
            float v2 = acc[mt][nt][2] + bx, v3 = acc[mt][nt][3] + by;
            if (RELU) {
                v0 = fmaxf(v0, 0.f); v1 = fmaxf(v1, 0.f);
                v2 = fmaxf(v2, 0.f); v3 = fmaxf(v3, 0.f);
            }
            if (r0 < M) *(float2*)(C + (size_t)r0 * N + cb) = make_float2(v0, v1);
            if (r1 < M) *(float2*)(C + (size_t)r1 * N + cb) = make_float2(v2, v3);
        }
    }
}

// ---------------- final linear ------------------------------------------------
__global__ void initout_k(const float* __restrict__ linb, float* __restrict__ out) {
    int i = threadIdx.x;
    if (i < 10) out[i] = linb[i];
}

__global__ void __launch_bounds__(256) final_k(const float* __restrict__ h,
                                               const float* __restrict__ W,
                                               float* __restrict__ out) {
    const int NT = NN2 * 256;
    const int NT4 = NT / 4;
    float acc[10];
#pragma unroll
    for (int r = 0; r < 10; r++) acc[r] = 0.f;
    int stride = gridDim.x * blockDim.x;
    const float4* h4 = (const float4*)h;
    for (int idx = blockIdx.x * blockDim.x + threadIdx.x; idx < NT4; idx += stride) {
        float4 hv = h4[idx];
#pragma unroll
        for (int r = 0; r < 10; r++) {
            float4 wv = *(const float4*)(W + (size_t)r * NT + idx * 4);
            acc[r] += hv.x * wv.x + hv.y * wv.y + hv.z * wv.z + hv.w * wv.w;
        }
    }
#pragma unroll
    for (int off = 16; off; off >>= 1)
#pragma unroll
        for (int r = 0; r < 10; r++) acc[r] += __shfl_down_sync(0xffffffffu, acc[r], off);
    __shared__ float part[8][10];
    int warp = threadIdx.x >> 5, lane = threadIdx.x & 31;
    if (lane == 0)
        for (int r = 0; r < 10; r++) part[warp][r] = acc[r];
    __syncthreads();
    if (threadIdx.x < 10) {
        float s = 0.f;
#pragma unroll
        for (int wv = 0; wv < 8; wv++) s += part[wv][threadIdx.x];
        atomicAdd(&out[threadIdx.x], s);
    }
}

// ---------------- host orchestration ----------------------------------------
extern "C" void kernel_launch(void* const* d_in, const int* in_sizes, int n_in,
                              void* d_out, int out_size) {
    const float* x    = (const float*)d_in[0];
    const int*   ei0  = (const int*)d_in[1];
    const int*   ei1  = (const int*)d_in[2];
    const int*   ei2  = (const int*)d_in[3];
    const float* W0   = (const float*)d_in[4];
    const float* b0   = (const float*)d_in[5];
    const float* W1   = (const float*)d_in[6];
    const float* b1   = (const float*)d_in[7];
    const float* W2   = (const float*)d_in[8];
    const float* b2   = (const float*)d_in[9];
    const int*   D0r  = (const int*)d_in[10];
    const int*   D0c  = (const int*)d_in[11];
    const float* D0v  = (const float*)d_in[12];
    const int*   D1r  = (const int*)d_in[13];
    const int*   D1c  = (const int*)d_in[14];
    const float* D1v  = (const float*)d_in[15];
    const float* linW = (const float*)d_in[16];
    const float* linb = (const float*)d_in[17];
    float* out = (float*)d_out;

    float *dinv0, *dinv1, *dinv2, *w0, *w1, *w2;
    float *T0, *h0, *T1, *h1, *T2, *h2;
    cudaGetSymbolAddress((void**)&dinv0, g_dinv0);
    cudaGetSymbolAddress((void**)&dinv1, g_dinv1);
    cudaGetSymbolAddress((void**)&dinv2, g_dinv2);
    cudaGetSymbolAddress((void**)&w0, g_w0);
    cudaGetSymbolAddress((void**)&w1, g_w1);
    cudaGetSymbolAddress((void**)&w2, g_w2);
    cudaGetSymbolAddress((void**)&T0, g_T0);
    cudaGetSymbolAddress((void**)&h0, g_h0);
    cudaGetSymbolAddress((void**)&T1, g_T1);
    cudaGetSymbolAddress((void**)&h1, g_h1);
    cudaGetSymbolAddress((void**)&T2, g_T2);
    cudaGetSymbolAddress((void**)&h2, g_h2);

    const int TB = 256;
    const int NTOT = NN0 + NN1 + NN2;
    const int ETOT = EE0 + EE1 + EE2;

    // preprocessing: normalized edge weights, all graphs fused
    zero_all_k<<<cdiv(NTOT, TB), TB>>>(dinv0, dinv1, dinv2);
    deg_all_k<<<cdiv(ETOT, TB), TB>>>(ei0, ei1, ei2, dinv0, dinv1, dinv2);
    dinv_all_k<<<cdiv(NTOT, TB), TB>>>(dinv0, dinv1, dinv2);
    ew_all_k<<<cdiv(ETOT, TB), TB>>>(ei0, ei1, ei2, dinv0, dinv1, dinv2, w0, w1, w2);

    // ---- layer 0 (F=3, RS=18) ----
    {
        initT0_k<<<cdiv(NN0 * 6, TB), TB>>>(T0, x);
        int sb = cdiv(NN0 * 3, TB);
        int eb = cdiv(EE0, TB);
        // k=1: scatter col1 += w*col0 ; also init col2 = -col0
        fused3_k<<<sb + eb, TB>>>(ei0, EE0, w0, 1.f, T0, 0, 3, 6, 0, sb);
        // k=2..4: scatter col k += 2w*col(k-1); init col(k+1) = -col(k-1)
        fused3_k<<<sb + eb, TB>>>(ei0, EE0, w0, 2.f, T0, 3, 6, 9, 3, sb);
        fused3_k<<<sb + eb, TB>>>(ei0, EE0, w0, 2.f, T0, 6, 9, 12, 6, sb);
        fused3_k<<<sb + eb, TB>>>(ei0, EE0, w0, 2.f, T0, 9, 12, 15, 9, sb);
        // k=5: scatter only
        fused3_k<<<eb, TB>>>(ei0, EE0, w0, 2.f, T0, 12, 15, 0, 0, 0);
        gemm0_k<<<cdiv(NN0, 8), 256>>>(T0, W0, b0, h0);
    }

    // ---- pool 0: h0 [N0,128] -> T1 col0 ----
    zero2_k<<<cdiv(NN1 * 64, TB), TB>>>(T1, NN1);
    pool_k<<<cdiv(100000 * 32, TB), TB>>>(D0r, D0c, D0v, 100000, h0, T1);

    // ---- layer 1 (F=128, RS=768) ----
    {
        int sb = cdiv(NN1 * 32, TB);
        int eb = cdiv(EE1 * 32, TB);
        fused128_k<<<sb + eb, TB>>>(ei1, EE1, w1, 1.f, T1, 0, 128, 256, 0, NN1, sb);
        fused128_k<<<sb + eb, TB>>>(ei1, EE1, w1, 2.f, T1, 128, 256, 384, 128, NN1, sb);
        fused128_k<<<sb + eb, TB>>>(ei1, EE1, w1, 2.f, T1, 256, 384, 512, 256, NN1, sb);
        fused128_k<<<sb + eb, TB>>>(ei1, EE1, w1, 2.f, T1, 384, 512, 640, 384, NN1, sb);
        fused128_k<<<eb, TB>>>(ei1, EE1, w1, 2.f, T1, 512, 640, 0, 0, NN1, 0);
        dim3 grid(1, cdiv(NN1, 64));
        gemm_tf32_k<true><<<grid, 256>>>(T1, W1, b1, h1, NN1, 128, 768);
    }

    // ---- pool 1: h1 [N1,128] -> T2 col0 ----
    zero2_k<<<cdiv(NN2 * 64, TB), TB>>>(T2, NN2);
    pool_k<<<cdiv(25000 * 32, TB), TB>>>(D1r, D1c, D1v, 25000, h1, T2);

    // ---- layer 2 (F=128, RS=768, out 256, no relu) ----
    {
        int sb = cdiv(NN2 * 32, TB);
        int eb = cdiv(EE2 * 32, TB);
        fused128_k<<<sb + eb, TB>>>(ei2, EE2, w2, 1.f, T2, 0, 128, 256, 0, NN2, sb);
        fused128_k<<<sb + eb, TB>>>(ei2, EE2, w2, 2.f, T2, 128, 256, 384, 128, NN2, sb);
        fused128_k<<<sb + eb, TB>>>(ei2, EE2, w2, 2.f, T2, 256, 384, 512, 256, NN2, sb);
        fused128_k<<<sb + eb, TB>>>(ei2, EE2, w2, 2.f, T2, 384, 512, 640, 384, NN2, sb);
        fused128_k<<<eb, TB>>>(ei2, EE2, w2, 2.f, T2, 512, 640, 0, 0, NN2, 0);
        dim3 grid(2, cdiv(NN2, 64));
        gemm_tf32_k<false><<<grid, 256>>>(T2, W2, b2, h2, NN2, 256, 768);
    }

    // ---- final linear ----
    initout_k<<<1, 32>>>(linb, out);
    final_k<<<592, 256>>>(h2, linW, out);
}

// round 7
// speedup vs baseline: 2.9735x; 1.2915x over previous
#include <cuda_runtime.h>

#define NN0 100000
#define NN1 25000
#define NN2 6250
#define EE0 600000
#define EE1 150000
#define EE2 37500
#define ED0 100000
#define ED1 25000

// concatenated count bases: [g0][g1][g2][D0 rows][D1 rows]
#define CB0 0
#define CB1 NN0
#define CB2 (NN0 + NN1)
#define CBD0 (NN0 + NN1 + NN2)
#define CBD1 (CBD0 + NN1)
#define CNT_TOT (CBD1 + NN2)                 // 162500
#define ETOT_ALL (EE0 + EE1 + EE2 + ED0 + ED1)  // 912500
#define SCAN_BLK 1024
#define NSCAN_BLKS ((CNT_TOT + SCAN_BLK - 1) / SCAN_BLK)  // 159

// ---------------- scratch (device globals; no allocations allowed) ----------
__device__ __align__(16) float g_dinv0[NN0], g_dinv1[NN1], g_dinv2[NN2];
__device__ __align__(16) int g_cnt[CNT_TOT];
__device__ __align__(16) int g_scan[CNT_TOT];
__device__ __align__(16) int g_rowptr[CNT_TOT];
__device__ __align__(16) int g_fill[CNT_TOT];
__device__ __align__(16) int g_bsum[NSCAN_BLKS];
__device__ __align__(16) int g_boff[NSCAN_BLKS];
__device__ __align__(16) int2 g_epack[ETOT_ALL];   // (src, w bits)
__device__ __align__(16) float g_T0[(size_t)NN0 * 24];   // 6 planes of [NN0,4]
__device__ __align__(16) float g_h0[(size_t)NN0 * 128];
__device__ __align__(16) float g_T1[(size_t)NN1 * 768];
__device__ __align__(16) float g_h1[(size_t)NN1 * 128];
__device__ __align__(16) float g_T2[(size_t)NN2 * 768];
__device__ __align__(16) float g_h2[(size_t)NN2 * 256];

static inline int cdiv(int a, int b) { return (a + b - 1) / b; }

// ---------------- helpers ----------------------------------------------------
__device__ __forceinline__ float tf32r(float x) {
    unsigned u;
    asm("cvt.rna.tf32.f32 %0, %1;" : "=r"(u) : "f"(x));
    return __uint_as_float(u);
}

__device__ __forceinline__ void mma_tf32(float& c0, float& c1, float& c2, float& c3,
                                         unsigned a0, unsigned a1, unsigned a2, unsigned a3,
                                         unsigned b0, unsigned b1) {
    asm volatile(
        "mma.sync.aligned.m16n8k8.row.col.f32.tf32.tf32.f32 "
        "{%0,%1,%2,%3},{%4,%5,%6,%7},{%8,%9},{%0,%1,%2,%3};"
        : "+f"(c0), "+f"(c1), "+f"(c2), "+f"(c3)
        : "r"(a0), "r"(a1), "r"(a2), "r"(a3), "r"(b0), "r"(b1));
}

// ---------------- CSR build ---------------------------------------------------
// zero cnt (int) + all dinv (float)
__global__ void zero_k(int* __restrict__ cnt, float* d0, float* d1, float* d2) {
    int i = blockIdx.x * blockDim.x + threadIdx.x;
    if (i < CNT_TOT) cnt[i] = 0;
    if (i < NN0) d0[i] = 0.f;
    int j = i - NN0;
    if (j >= 0 && j < NN1) d1[j] = 0.f;
    int k = j - NN1;
    if (k >= 0 && k < NN2) d2[k] = 0.f;
}

// out-degree (float, by src, for dinv) + in-degree histogram (int, by dst)
__global__ void hist_k(const int* e0, const int* e1, const int* e2,
                       const int* d0r, const int* d1r,
                       float* dv0, float* dv1, float* dv2, int* __restrict__ cnt) {
    int i = blockIdx.x * blockDim.x + threadIdx.x;
    if (i < EE0) {
        atomicAdd(&dv0[e0[i]], 1.f);
        atomicAdd(&cnt[CB0 + e0[EE0 + i]], 1);
        return;
    }
    i -= EE0;
    if (i < EE1) {
        atomicAdd(&dv1[e1[i]], 1.f);
        atomicAdd(&cnt[CB1 + e1[EE1 + i]], 1);
        return;
    }
    i -= EE1;
    if (i < EE2) {
        atomicAdd(&dv2[e2[i]], 1.f);
        atomicAdd(&cnt[CB2 + e2[EE2 + i]], 1);
        return;
    }
    i -= EE2;
    if (i < ED0) { atomicAdd(&cnt[CBD0 + d0r[i]], 1); return; }
    i -= ED0;
    if (i < ED1) atomicAdd(&cnt[CBD1 + d1r[i]], 1);
}

__global__ void dinv_k(float* d0, float* d1, float* d2) {
    int i = blockIdx.x * blockDim.x + threadIdx.x;
    if (i < NN0) { float v = d0[i]; d0[i] = v > 0.f ? rsqrtf(v) : 0.f; }
    int j = i - NN0;
    if (j >= 0 && j < NN1) { float v = d1[j]; d1[j] = v > 0.f ? rsqrtf(v) : 0.f; }
    int k = j - NN1;
    if (k >= 0 && k < NN2) { float v = d2[k]; d2[k] = v > 0.f ? rsqrtf(v) : 0.f; }
}

// per-block inclusive scan (1024 threads)
__global__ void scan1_k(const int* __restrict__ cnt, int* __restrict__ scn,
                        int* __restrict__ bsum) {
    __shared__ int sm[SCAN_BLK];
    int t = threadIdx.x;
    int gid = blockIdx.x * SCAN_BLK + t;
    int v = (gid < CNT_TOT) ? cnt[gid] : 0;
    sm[t] = v;
    __syncthreads();
    for (int off = 1; off < SCAN_BLK; off <<= 1) {
        int add = (t >= off) ? sm[t - off] : 0;
        __syncthreads();
        sm[t] += add;
        __syncthreads();
    }
    if (gid < CNT_TOT) scn[gid] = sm[t];
    if (t == SCAN_BLK - 1) bsum[blockIdx.x] = sm[t];
}

// serial exclusive scan of block sums (tiny)
__global__ void scan2_k(const int* __restrict__ bsum, int* __restrict__ boff) {
    if (threadIdx.x == 0) {
        int acc = 0;
        for (int i = 0; i < NSCAN_BLKS; i++) { boff[i] = acc; acc += bsum[i]; }
    }
}

// exclusive start positions -> rowptr and fill cursors
__global__ void scan3_k(const int* __restrict__ cnt, const int* __restrict__ scn,
                        const int* __restrict__ boff, int* __restrict__ rowptr,
                        int* __restrict__ fill) {
    int i = blockIdx.x * blockDim.x + threadIdx.x;
    if (i >= CNT_TOT) return;
    int start = scn[i] - cnt[i] + boff[i / SCAN_BLK];
    rowptr[i] = start;
    fill[i] = start;
}

// fill CSR edge arrays: (src, weight) packed, grouped by dst
__global__ void fill_k(const int* e0, const int* e1, const int* e2,
                       const int* d0r, const int* d0c, const float* d0v,
                       const int* d1r, const int* d1c, const float* d1v,
                       const float* dv0, const float* dv1, const float* dv2,
                       int* __restrict__ fill, int2* __restrict__ ep) {
    int i = blockIdx.x * blockDim.x + threadIdx.x;
    int src, cb; float w;
    if (i < EE0) {
        src = e0[i]; int dst = e0[EE0 + i];
        w = -dv0[src] * dv0[dst]; cb = CB0 + dst;
    } else if ((i -= EE0) < EE1) {
        src = e1[i]; int dst = e1[EE1 + i];
        w = -dv1[src] * dv1[dst]; cb = CB1 + dst;
    } else if ((i -= EE1) < EE2) {
        src = e2[i]; int dst = e2[EE2 + i];
        w = -dv2[src] * dv2[dst]; cb = CB2 + dst;
    } else if ((i -= EE2) < ED0) {
        src = d0c[i]; w = d0v[i]; cb = CBD0 + d0r[i];
    } else if ((i -= ED0) < ED1) {
        src = d1c[i]; w = d1v[i]; cb = CBD1 + d1r[i];
    } else return;
    int pos = atomicAdd(&fill[cb], 1);
    ep[pos] = make_int2(src, __float_as_int(w));
}

// ---------------- layer-0 (F=3, padded to 4; 6 planes) -----------------------
__global__ void initT0_k(float* __restrict__ T, const float* __restrict__ x) {
    int i = blockIdx.x * blockDim.x + threadIdx.x;
    if (i >= NN0) return;
    *(float4*)(T + (size_t)i * 4) =
        make_float4(x[i * 3], x[i * 3 + 1], x[i * 3 + 2], 0.f);
}

// thread per dst node: out_plane = coef * sum_e w*in_plane[src]  (- prev_plane)
template <bool SUB>
__global__ void gather3_k(const int* __restrict__ rowptr, const int* __restrict__ cnt,
                          const int2* __restrict__ ep, float* __restrict__ T,
                          float coef, int in_p, int out_p, int prev_p) {
    int node = blockIdx.x * blockDim.x + threadIdx.x;
    if (node >= NN0) return;
    int s = rowptr[node], n = cnt[node];
    const float* Tin = T + (size_t)in_p * NN0 * 4;
    float4 acc = make_float4(0.f, 0.f, 0.f, 0.f);
#pragma unroll 4
    for (int i = 0; i < n; i++) {
        int2 p = ep[s + i];
        float w = __int_as_float(p.y);
        float4 xv = *(const float4*)(Tin + (size_t)p.x * 4);
        acc.x = fmaf(w, xv.x, acc.x); acc.y = fmaf(w, xv.y, acc.y);
        acc.z = fmaf(w, xv.z, acc.z);
    }
    float4 o;
    if (SUB) {
        float4 pr = *(const float4*)(T + ((size_t)prev_p * NN0 + node) * 4);
        o = make_float4(coef * acc.x - pr.x, coef * acc.y - pr.y,
                        coef * acc.z - pr.z, 0.f);
    } else {
        o = make_float4(coef * acc.x, coef * acc.y, coef * acc.z, 0.f);
    }
    *(float4*)(T + ((size_t)out_p * NN0 + node) * 4) = o;
}

// h0 = relu(T0(planes) @ W[18,128] + b), W in smem, warp per node
__global__ void __launch_bounds__(256) gemm0_k(const float* __restrict__ T,
                                               const float* __restrict__ W,
                                               const float* __restrict__ bias,
                                               float* __restrict__ out) {
    __shared__ float Ws[18 * 128];
    __shared__ float Bsm[128];
    int tid = threadIdx.x;
    for (int i = tid; i < 18 * 128; i += 256) Ws[i] = W[i];
    if (tid < 128) Bsm[tid] = bias[tid];
    __syncthreads();
    int node = blockIdx.x * 8 + (tid >> 5);
    if (node >= NN0) return;
    int c0 = (tid & 31) * 4;
    float tv[18];
#pragma unroll
    for (int p = 0; p < 6; p++) {
        float4 t4 = *(const float4*)(T + ((size_t)p * NN0 + node) * 4);
        tv[p * 3 + 0] = t4.x; tv[p * 3 + 1] = t4.y; tv[p * 3 + 2] = t4.z;
    }
    float a0 = Bsm[c0], a1 = Bsm[c0 + 1], a2 = Bsm[c0 + 2], a3 = Bsm[c0 + 3];
#pragma unroll
    for (int k = 0; k < 18; k++) {
        float t = tv[k];
        const float4 w4 = *(const float4*)(Ws + k * 128 + c0);
        a0 = fmaf(t, w4.x, a0); a1 = fmaf(t, w4.y, a1);
        a2 = fmaf(t, w4.z, a2); a3 = fmaf(t, w4.w, a3);
    }
    *(float4*)(out + (size_t)node * 128 + c0) =
        make_float4(fmaxf(a0, 0.f), fmaxf(a1, 0.f), fmaxf(a2, 0.f), fmaxf(a3, 0.f));
}

// ---------------- F=128 gather (warp per dst node) ----------------------------
// T[node*768 + out_off] = coef * sum_e w * Tin[src*in_stride + in_off] (- prev)
template <bool SUB>
__global__ void gather128_k(const int* __restrict__ rowptr, const int* __restrict__ cnt,
                            const int2* __restrict__ ep, int cbase,
                            const float* __restrict__ Tin, int in_stride, int in_off,
                            float* __restrict__ Tout,
                            float coef, int out_off, int prev_off, int nnodes) {
    int gw = (blockIdx.x * blockDim.x + threadIdx.x) >> 5;
    int lane = threadIdx.x & 31;
    if (gw >= nnodes) return;
    int s = rowptr[cbase + gw], n = cnt[cbase + gw];
    const float* ip = Tin + in_off + lane * 4;
    float4 acc = make_float4(0.f, 0.f, 0.f, 0.f);
#pragma unroll 4
    for (int i = 0; i < n; i++) {
        int2 p = ep[s + i];
        float w = __int_as_float(p.y);
        float4 xv = *(const float4*)(ip + (size_t)p.x * in_stride);
        acc.x = fmaf(w, xv.x, acc.x); acc.y = fmaf(w, xv.y, acc.y);
        acc.z = fmaf(w, xv.z, acc.z); acc.w = fmaf(w, xv.w, acc.w);
    }
    float4 o;
    if (SUB) {
        float4 pr = *(const float4*)(Tout + (size_t)gw * 768 + prev_off + lane * 4);
        o = make_float4(coef * acc.x - pr.x, coef * acc.y - pr.y,
                        coef * acc.z - pr.z, coef * acc.w - pr.w);
    } else {
        o = make_float4(coef * acc.x, coef * acc.y, coef * acc.z, coef * acc.w);
    }
    *(float4*)(Tout + (size_t)gw * 768 + out_off + lane * 4) = o;
}

// ---------------- tf32 tensor-core GEMM --------------------------------------
template <bool RELU>
__global__ void __launch_bounds__(256) gemm_tf32_k(const float* __restrict__ A,
                                                   const float* __restrict__ B,
                                                   const float* __restrict__ bias,
                                                   float* __restrict__ C,
                                                   int M, int N, int K) {
    __shared__ float As[2][16][68];
    __shared__ float Bs[2][16][132];
    const int tid = threadIdx.x;
    const int warp = tid >> 5, lane = tid & 31;
    const int g = lane >> 2, tg = lane & 3;
    const int m0 = (warp >> 2) * 32, n0 = (warp & 3) * 32;
    const int brow = blockIdx.y * 64, bcol = blockIdx.x * 128;

    const int am = tid >> 2, akq = (tid & 3) << 2;
    const int bk = tid >> 5, bn4 = (tid & 31) << 2;

    float acc[2][4][4];
#pragma unroll
    for (int i = 0; i < 2; i++)
#pragma unroll
        for (int j = 0; j < 4; j++)
#pragma unroll
            for (int q = 0; q < 4; q++) acc[i][j][q] = 0.f;

    const int KT = K / 16;
    float4 pa, pb0, pb1;
    {
        int gr = brow + am;
        pa = (gr < M) ? *(const float4*)(A + (size_t)gr * K + akq)
                      : make_float4(0.f, 0.f, 0.f, 0.f);
        pb0 = *(const float4*)(B + (size_t)bk * N + bcol + bn4);
        pb1 = *(const float4*)(B + (size_t)(bk + 8) * N + bcol + bn4);
        As[0][akq + 0][am] = tf32r(pa.x); As[0][akq + 1][am] = tf32r(pa.y);
        As[0][akq + 2][am] = tf32r(pa.z); As[0][akq + 3][am] = tf32r(pa.w);
        *(float4*)&Bs[0][bk][bn4] =
            make_float4(tf32r(pb0.x), tf32r(pb0.y), tf32r(pb0.z), tf32r(pb0.w));
        *(float4*)&Bs[0][bk + 8][bn4] =
            make_float4(tf32r(pb1.x), tf32r(pb1.y), tf32r(pb1.z), tf32r(pb1.w));
    }
    __syncthreads();

    for (int t = 0; t < KT; t++) {
        const int st = t & 1;
        if (t + 1 < KT) {
            int kk = (t + 1) * 16;
            int gr = brow + am;
            pa = (gr < M) ? *(const float4*)(A + (size_t)gr * K + kk + akq)
                          : make_float4(0.f, 0.f, 0.f, 0.f);
            pb0 = *(const float4*)(B + (size_t)(kk + bk) * N + bcol + bn4);
            pb1 = *(const float4*)(B + (size_t)(kk + bk + 8) * N + bcol + bn4);
        }
#pragma unroll
        for (int ks = 0; ks < 16; ks += 8) {
            unsigned af[2][4], bf[4][2];
#pragma unroll
            for (int mt = 0; mt < 2; mt++) {
                int mr = m0 + mt * 16 + g;
                af[mt][0] = __float_as_uint(As[st][ks + tg][mr]);
                af[mt][1] = __float_as_uint(As[st][ks + tg][mr + 8]);
                af[mt][2] = __float_as_uint(As[st][ks + tg + 4][mr]);
                af[mt][3] = __float_as_uint(As[st][ks + tg + 4][mr + 8]);
            }
#pragma unroll
            for (int nt = 0; nt < 4; nt++) {
                int nc = n0 + nt * 8 + g;
                bf[nt][0] = __float_as_uint(Bs[st][ks + tg][nc]);
                bf[nt][1] = __float_as_uint(Bs[st][ks + tg + 4][nc]);
            }
#pragma unroll
            for (int mt = 0; mt < 2; mt++)
#pragma unroll
                for (int nt = 0; nt < 4; nt++)
                    mma_tf32(acc[mt][nt][0], acc[mt][nt][1], acc[mt][nt][2], acc[mt][nt][3],
                             af[mt][0], af[mt][1], af[mt][2], af[mt][3],
                             bf[nt][0], bf[nt][1]);
        }
        __syncthreads();
        if (t + 1 < KT) {
            const int ns = (t + 1) & 1;
            As[ns][akq + 0][am] = tf32r(pa.x); As[ns][akq + 1][am] = tf32r(pa.y);
            As[ns][akq + 2][am] = tf32r(pa.z); As[ns][akq + 3][am] = tf32r(pa.w);
            *(float4*)&Bs[ns][bk][bn4] =
                make_float4(tf32r(pb0.x), tf32r(pb0.y), tf32r(pb0.z), tf32r(pb0.w));
            *(float4*)&Bs[ns][bk + 8][bn4] =
                make_float4(tf32r(pb1.x), tf32r(pb1.y), tf32r(pb1.z), tf32r(pb1.w));
            __syncthreads();
        }
    }

#pragma unroll
    for (int mt = 0; mt < 2; mt++) {
        int r0 = brow + m0 + mt * 16 + g;
        int r1 = r0 + 8;
#pragma unroll
        for (int nt = 0; nt < 4; nt++) {
            int cb = bcol + n0 + nt * 8 + 2 * tg;
            float bx = bias[cb], by = bias[cb + 1];
            float v0 = acc[mt][nt][0] + bx, v1 = acc[mt][nt][1] + by;
            float v2 = acc[mt][nt][2] + bx, v3 = acc[mt][nt][3] + by;
            if (RELU) {
                v0 = fmaxf(v0, 0.f); v1 = fmaxf(v1, 0.f);
                v2 = fmaxf(v2, 0.f); v3 = fmaxf(v3, 0.f);
            }
            if (r0 < M) *(float2*)(C + (size_t)r0 * N + cb) = make_float2(v0, v1);
            if (r1 < M) *(float2*)(C + (size_t)r1 * N + cb) = make_float2(v2, v3);
        }
    }
}

// ---------------- final linear ------------------------------------------------
__global__ void initout_k(const float* __restrict__ linb, float* __restrict__ out) {
    int i = threadIdx.x;
    if (i < 10) out[i] = linb[i];
}

__global__ void __launch_bounds__(256) final_k(const float* __restrict__ h,
                                               const float* __restrict__ W,
                                               float* __restrict__ out) {
    const int NT = NN2 * 256;
    const int NT4 = NT / 4;
    float acc[10];
#pragma unroll
    for (int r = 0; r < 10; r++) acc[r] = 0.f;
    int stride = gridDim.x * blockDim.x;
    const float4* h4 = (const float4*)h;
    for (int idx = blockIdx.x * blockDim.x + threadIdx.x; idx < NT4; idx += stride) {
        float4 hv = h4[idx];
#pragma unroll
        for (int r = 0; r < 10; r++) {
            float4 wv = *(const float4*)(W + (size_t)r * NT + idx * 4);
            acc[r] += hv.x * wv.x + hv.y * wv.y + hv.z * wv.z + hv.w * wv.w;
        }
    }
#pragma unroll
    for (int off = 16; off; off >>= 1)
#pragma unroll
        for (int r = 0; r < 10; r++) acc[r] += __shfl_down_sync(0xffffffffu, acc[r], off);
    __shared__ float part[8][10];
    int warp = threadIdx.x >> 5, lane = threadIdx.x & 31;
    if (lane == 0)
        for (int r = 0; r < 10; r++) part[warp][r] = acc[r];
    __syncthreads();
    if (threadIdx.x < 10) {
        float s = 0.f;
#pragma unroll
        for (int wv = 0; wv < 8; wv++) s += part[wv][threadIdx.x];
        atomicAdd(&out[threadIdx.x], s);
    }
}

// ---------------- host orchestration ----------------------------------------
extern "C" void kernel_launch(void* const* d_in, const int* in_sizes, int n_in,
                              void* d_out, int out_size) {
    const float* x    = (const float*)d_in[0];
    const int*   ei0  = (const int*)d_in[1];
    const int*   ei1  = (const int*)d_in[2];
    const int*   ei2  = (const int*)d_in[3];
    const float* W0   = (const float*)d_in[4];
    const float* b0   = (const float*)d_in[5];
    const float* W1   = (const float*)d_in[6];
    const float* b1   = (const float*)d_in[7];
    const float* W2   = (const float*)d_in[8];
    const float* b2   = (const float*)d_in[9];
    const int*   D0r  = (const int*)d_in[10];
    const int*   D0c  = (const int*)d_in[11];
    const float* D0v  = (const float*)d_in[12];
    const int*   D1r  = (const int*)d_in[13];
    const int*   D1c  = (const int*)d_in[14];
    const float* D1v  = (const float*)d_in[15];
    const float* linW = (const float*)d_in[16];
    const float* linb = (const float*)d_in[17];
    float* out = (float*)d_out;

    float *dinv0, *dinv1, *dinv2, *T0, *h0, *T1, *h1, *T2, *h2;
    int *cnt, *scn, *rowptr, *fill, *bsum, *boff;
    int2* ep;
    cudaGetSymbolAddress((void**)&dinv0, g_dinv0);
    cudaGetSymbolAddress((void**)&dinv1, g_dinv1);
    cudaGetSymbolAddress((void**)&dinv2, g_dinv2);
    cudaGetSymbolAddress((void**)&cnt, g_cnt);
    cudaGetSymbolAddress((void**)&scn, g_scan);
    cudaGetSymbolAddress((void**)&rowptr, g_rowptr);
    cudaGetSymbolAddress((void**)&fill, g_fill);
    cudaGetSymbolAddress((void**)&bsum, g_bsum);
    cudaGetSymbolAddress((void**)&boff, g_boff);
    cudaGetSymbolAddress((void**)&ep, g_epack);
    cudaGetSymbolAddress((void**)&T0, g_T0);
    cudaGetSymbolAddress((void**)&h0, g_h0);
    cudaGetSymbolAddress((void**)&T1, g_T1);
    cudaGetSymbolAddress((void**)&h1, g_h1);
    cudaGetSymbolAddress((void**)&T2, g_T2);
    cudaGetSymbolAddress((void**)&h2, g_h2);

    const int TB = 256;

    // ---- CSR build (all 3 graphs + 2 pool matrices, concatenated) ----
    zero_k<<<cdiv(CNT_TOT, TB), TB>>>(cnt, dinv0, dinv1, dinv2);
    hist_k<<<cdiv(ETOT_ALL, TB), TB>>>(ei0, ei1, ei2, D0r, D1r,
                                       dinv0, dinv1, dinv2, cnt);
    dinv_k<<<cdiv(NN0 + NN1 + NN2, TB), TB>>>(dinv0, dinv1, dinv2);
    scan1_k<<<NSCAN_BLKS, SCAN_BLK>>>(cnt, scn, bsum);
    scan2_k<<<1, 32>>>(bsum, boff);
    scan3_k<<<cdiv(CNT_TOT, TB), TB>>>(cnt, scn, boff, rowptr, fill);
    fill_k<<<cdiv(ETOT_ALL, TB), TB>>>(ei0, ei1, ei2, D0r, D0c, D0v,
                                       D1r, D1c, D1v, dinv0, dinv1, dinv2, fill, ep);

    // ---- layer 0 (6 planes of [NN0,4]) ----
    initT0_k<<<cdiv(NN0, TB), TB>>>(T0, x);
    gather3_k<false><<<cdiv(NN0, TB), TB>>>(rowptr, cnt, ep, T0, 1.f, 0, 1, 0);
    gather3_k<true><<<cdiv(NN0, TB), TB>>>(rowptr, cnt, ep, T0, 2.f, 1, 2, 0);
    gather3_k<true><<<cdiv(NN0, TB), TB>>>(rowptr, cnt, ep, T0, 2.f, 2, 3, 1);
    gather3_k<true><<<cdiv(NN0, TB), TB>>>(rowptr, cnt, ep, T0, 2.f, 3, 4, 2);
    gather3_k<true><<<cdiv(NN0, TB), TB>>>(rowptr, cnt, ep, T0, 2.f, 4, 5, 3);
    gemm0_k<<<cdiv(NN0, 8), 256>>>(T0, W0, b0, h0);

    // ---- pool 0 (gather): h0 [N0,128] -> T1 col0 ----
    gather128_k<false><<<cdiv(NN1 * 32, TB), TB>>>(rowptr, cnt, ep, CBD0, h0, 128, 0,
                                                   T1, 1.f, 0, 0, NN1);

    // ---- layer 1 (gathers within T1, stride 768) ----
    gather128_k<false><<<cdiv(NN1 * 32, TB), TB>>>(rowptr, cnt, ep, CB1, T1, 768, 0,
                                                   T1, 1.f, 128, 0, NN1);
    gather128_k<true><<<cdiv(NN1 * 32, TB), TB>>>(rowptr, cnt, ep, CB1, T1, 768, 128,
                                                  T1, 2.f, 256, 0, NN1);
    gather128_k<true><<<cdiv(NN1 * 32, TB), TB>>>(rowptr, cnt, ep, CB1, T1, 768, 256,
                                                  T1, 2.f, 384, 128, NN1);
    gather128_k<true><<<cdiv(NN1 * 32, TB), TB>>>(rowptr, cnt, ep, CB1, T1, 768, 384,
                                                  T1, 2.f, 512, 256, NN1);
    gather128_k<true><<<cdiv(NN1 * 32, TB), TB>>>(rowptr, cnt, ep, CB1, T1, 768, 512,
                                                  T1, 2.f, 640, 384, NN1);
    {
        dim3 grid(1, cdiv(NN1, 64));
        gemm_tf32_k<true><<<grid, 256>>>(T1, W1, b1, h1, NN1, 128, 768);
    }

    // ---- pool 1 (gather): h1 [N1,128] -> T2 col0 ----
    gather128_k<false><<<cdiv(NN2 * 32, TB), TB>>>(rowptr, cnt, ep, CBD1, h1, 128, 0,
                                                   T2, 1.f, 0, 0, NN2);

    // ---- layer 2 ----
    gather128_k<false><<<cdiv(NN2 * 32, TB), TB>>>(rowptr, cnt, ep, CB2, T2, 768, 0,
                                                   T2, 1.f, 128, 0, NN2);
    gather128_k<true><<<cdiv(NN2 * 32, TB), TB>>>(rowptr, cnt, ep, CB2, T2, 768, 128,
                                                  T2, 2.f, 256, 0, NN2);
    gather128_k<true><<<cdiv(NN2 * 32, TB), TB>>>(rowptr, cnt, ep, CB2, T2, 768, 256,
                                                  T2, 2.f, 384, 128, NN2);
    gather128_k<true><<<cdiv(NN2 * 32, TB), TB>>>(rowptr, cnt, ep, CB2, T2, 768, 384,
                                                  T2, 2.f, 512, 256, NN2);
    gather128_k<true><<<cdiv(NN2 * 32, TB), TB>>>(rowptr, cnt, ep, CB2, T2, 768, 512,
                                                  T2, 2.f, 640, 384, NN2);
    {
        dim3 grid(2, cdiv(NN2, 64));
        gemm_tf32_k<false><<<grid, 256>>>(T2, W2, b2, h2, NN2, 256, 768);
    }

    // ---- final linear ----
    initout_k<<<1, 32>>>(linb, out);
    final_k<<<592, 256>>>(h2, linW, out);
}